// round 15
// baseline (speedup 1.0000x reference)
#include <cuda_runtime.h>
#include <math.h>

#define FS    39      // total fields
#define NF    38      // fields in pairwise term (0..37)
#define NP    703     // NF*(NF-1)/2 pairs
#define FEAT  100000
#define EMB   10
#define ROWB  (EMB*4) // 40 bytes per embedding row
#define TPB   128
#define KMAX  28      // ceil(703*5 / 128)
#define NPPAD 720     // padded pair table (max p touched = 707)

// Gather with L1 bypass (.cg = cache at L2 only): gathered lines have ~0%
// L1 reuse, so skipping L1 allocation removes tag/fill work from the L1
// pipeline without losing any hits.
__device__ __forceinline__ float2 ldg_cg(const char* p) {
    float2 r;
    asm("ld.global.cg.v2.f32 {%0, %1}, [%2];"
        : "=f"(r.x), "=f"(r.y) : "l"(p));
    return r;
}

__global__ __launch_bounds__(TPB) void ffm_kernel(
    const int*   __restrict__ idxs,   // [B, FS]
    const float* __restrict__ vals,   // [B, FS]
    const float* __restrict__ emb,    // [FS, FEAT, EMB]
    const float* __restrict__ w1,     // [FEAT]
    float*       __restrict__ out)    // [B]
{
    __shared__ int   s_idx[FS];
    __shared__ float s_val[FS];
    __shared__ int4  s_pair[NPPAD];   // {byteOffA, byteOffB, bits(v_i*v_j), pad}
    __shared__ float s_red[TPB / 32];

    const int b = blockIdx.x;
    const int t = threadIdx.x;

    if (t < FS) {
        s_idx[t] = idxs[b * FS + t];
        s_val[t] = vals[b * FS + t];
    }
    __syncthreads();

    // Zero-scale padding so the main loop needs no bounds guard.
    for (int p = NP + t; p < NPPAD; p += TPB) {
        s_pair[p] = make_int4(0, 0, 0, 0);
    }

    // Prologue: closed-form triangular decode p -> (i, j); byte-offset
    // descriptors. base(i) = i*(75-i)/2 for NF=38.
    for (int p = t; p < NP; p += TPB) {
        int i = (int)((75.0f - sqrtf(5625.0f - 8.0f * (float)p)) * 0.5f);
        if (p < i * (75 - i) / 2) --i;
        else if (p >= (i + 1) * (74 - i) / 2) ++i;
        const int base = i * (75 - i) / 2;
        const int j = p - base + i + 1;
        int4 d;
        d.x = (i * FEAT + s_idx[j]) * ROWB;   // emb[i][idx_j] byte offset
        d.y = (j * FEAT + s_idx[i]) * ROWB;   // emb[j][idx_i] byte offset
        d.z = __float_as_int(s_val[i] * s_val[j]);
        d.w = 0;
        s_pair[p] = d;
    }

    float acc = 0.f, acc2 = 0.f;
    if (t < FS) {
        acc = w1[s_idx[t]] * s_val[t];        // first-order term
    }
    __syncthreads();

    // Main loop: uniform 28 items/thread. Per item: 1 LDS.128 + 2 LDG.64(cg)
    // + 3 FFMA + incremental (p, chunk-byte) update. Stride 128 = 25*5 + 3,
    // so per step: p += 25, cb += 24, wrap once if cb >= 40.
    const char* __restrict__ embB = (const char*)emb;
    int p  = t / 5;
    int cb = (t - p * 5) * 8;

    #pragma unroll
    for (int k = 0; k < KMAX; ++k) {
        const int4 d = s_pair[p];
        const float2 a = ldg_cg(embB + (unsigned)(d.x + cb));
        const float2 v = ldg_cg(embB + (unsigned)(d.y + cb));
        const float s = __int_as_float(d.z);
        if (k & 1) acc2 += s * (a.x * v.x + a.y * v.y);
        else       acc  += s * (a.x * v.x + a.y * v.y);
        p += 25; cb += 24;
        if (cb >= ROWB) { cb -= ROWB; ++p; }
    }
    acc += acc2;

    // Block reduction (4 warps).
    #pragma unroll
    for (int o = 16; o > 0; o >>= 1)
        acc += __shfl_down_sync(0xffffffffu, acc, o);
    if ((t & 31) == 0) s_red[t >> 5] = acc;
    __syncthreads();
    if (t == 0) {
        float tot = 0.f;
        #pragma unroll
        for (int w = 0; w < TPB / 32; w++) tot += s_red[w];
        out[b] = 1.f / (1.f + expf(-tot));
    }
}

extern "C" void kernel_launch(void* const* d_in, const int* in_sizes, int n_in,
                              void* d_out, int out_size) {
    const int*   idxs = (const int*)d_in[0];
    const float* vals = (const float*)d_in[1];
    const float* emb  = (const float*)d_in[2];
    const float* w1   = (const float*)d_in[3];
    float* out = (float*)d_out;

    const int batch = out_size;  // 2048
    ffm_kernel<<<batch, TPB>>>(idxs, vals, emb, w1, out);
}

// round 16
// speedup vs baseline: 1.1089x; 1.1089x over previous
#include <cuda_runtime.h>
#include <math.h>

#define FS    39      // total fields
#define NF    38      // fields in pairwise term (0..37)
#define NP    703     // NF*(NF-1)/2 pairs
#define FEAT  100000
#define EMB   10
#define ROWB  (EMB*4) // 40 bytes per embedding row
#define TPB   256
#define KMAX  14      // ceil(703*5 / 256)
#define NPPAD 720     // padded pair table (max slot touched = 716)
#define W     19      // field-block width (2 groups of 19)

// Gather with L1 bypass (.cg): gathered lines have ~0% L1 reuse.
__device__ __forceinline__ float2 ldg_cg(const char* p) {
    float2 r;
    asm("ld.global.cg.v2.f32 {%0, %1}, [%2];"
        : "=f"(r.x), "=f"(r.y) : "l"(p));
    return r;
}

__global__ __launch_bounds__(TPB) void ffm_kernel(
    const int*   __restrict__ idxs,   // [B, FS]
    const float* __restrict__ vals,   // [B, FS]
    const float* __restrict__ emb,    // [FS, FEAT, EMB]
    const float* __restrict__ w1,     // [FEAT]
    float*       __restrict__ out)    // [B]
{
    __shared__ int   s_idx[FS];
    __shared__ float s_val[FS];
    __shared__ int4  s_pair[NPPAD];   // block-sorted descriptors
    __shared__ float s_red[TPB / 32];

    const int b = blockIdx.x;
    const int t = threadIdx.x;

    if (t < FS) {
        s_idx[t] = idxs[b * FS + t];
        s_val[t] = vals[b * FS + t];
    }
    __syncthreads();

    // Zero-scale padding so the main loop needs no bounds guard.
    for (int p = NP + t; p < NPPAD; p += TPB) {
        s_pair[p] = make_int4(0, 0, 0, 0);
    }

    // Prologue: decode pair p -> (i, j) (closed form), then scatter the
    // descriptor to its FIELD-BLOCK-SORTED slot. Blocks over groups
    // {0..18} (lo) and {19..37} (hi):
    //   B0 = (lo,lo): slots [0,171)    B1 = (lo,hi): slots [171,532)
    //   B2 = (hi,hi): slots [532,703)
    // All CTAs sweep slots in the same order in rough lockstep, so each
    // episode's table working set (<= 94MB) stays L2-resident chip-wide,
    // capturing cross-batch granule-collision reuse.
    for (int p = t; p < NP; p += TPB) {
        int i = (int)((75.0f - sqrtf(5625.0f - 8.0f * (float)p)) * 0.5f);
        if (p < i * (75 - i) / 2) --i;
        else if (p >= (i + 1) * (74 - i) / 2) ++i;
        const int base = i * (75 - i) / 2;
        const int j = p - base + i + 1;

        int slot;
        if (j < W) {                       // B0: both lo
            slot = i * (2 * W - i - 1) / 2 + (j - i - 1);
        } else if (i < W) {                // B1: lo x hi
            slot = 171 + i * W + (j - W);
        } else {                           // B2: both hi
            const int ii = i - W;
            slot = 532 + ii * (2 * W - ii - 1) / 2 + (j - i - 1);
        }

        int4 d;
        d.x = (i * FEAT + s_idx[j]) * ROWB;   // emb[i][idx_j] byte offset
        d.y = (j * FEAT + s_idx[i]) * ROWB;   // emb[j][idx_i] byte offset
        d.z = __float_as_int(s_val[i] * s_val[j]);
        d.w = 0;
        s_pair[slot] = d;
    }

    float acc = 0.f, acc2 = 0.f;
    if (t < FS) {
        acc = w1[s_idx[t]] * s_val[t];        // first-order term
    }
    __syncthreads();

    // Main loop (identical to champion): uniform 14 items/thread,
    // incremental (slot, chunk-byte) stepping (stride 256 = 51*5 + 1).
    const char* __restrict__ embB = (const char*)emb;
    int p  = t / 5;
    int cb = (t - p * 5) * 8;

    #pragma unroll
    for (int k = 0; k < KMAX; ++k) {
        const int4 d = s_pair[p];
        const float2 a = ldg_cg(embB + (unsigned)(d.x + cb));
        const float2 v = ldg_cg(embB + (unsigned)(d.y + cb));
        const float s = __int_as_float(d.z);
        if (k & 1) acc2 += s * (a.x * v.x + a.y * v.y);
        else       acc  += s * (a.x * v.x + a.y * v.y);
        p += 51; cb += 8;
        if (cb >= ROWB) { cb -= ROWB; ++p; }
    }
    acc += acc2;

    // Block reduction.
    #pragma unroll
    for (int o = 16; o > 0; o >>= 1)
        acc += __shfl_down_sync(0xffffffffu, acc, o);
    if ((t & 31) == 0) s_red[t >> 5] = acc;
    __syncthreads();
    if (t == 0) {
        float tot = 0.f;
        #pragma unroll
        for (int w = 0; w < TPB / 32; w++) tot += s_red[w];
        out[b] = 1.f / (1.f + expf(-tot));
    }
}

extern "C" void kernel_launch(void* const* d_in, const int* in_sizes, int n_in,
                              void* d_out, int out_size) {
    const int*   idxs = (const int*)d_in[0];
    const float* vals = (const float*)d_in[1];
    const float* emb  = (const float*)d_in[2];
    const float* w1   = (const float*)d_in[3];
    float* out = (float*)d_out;

    const int batch = out_size;  // 2048
    ffm_kernel<<<batch, TPB>>>(idxs, vals, emb, w1, out);
}